// round 13
// baseline (speedup 1.0000x reference)
#include <cuda_runtime.h>
#include <cstdint>

#define kB   4
#define kDEC 256
#define kENC 1024
#define kHID 512
#define kU   128

#define QSPLIT 8
#define KSPLIT 8
#define CSPLIT 8

#define QP_STRIDE (1024 * 128)   // one qproj part
#define KP_STRIDE (4096 * 128)   // one kproj part
#define CP_STRIDE (256 * 512)    // one ctx part

// score smem: 2048(qs) + 128(scl) + 128*132(ks) floats = 76,288 B -> 2 CTAs/SM
#define SCORE_SMEM_FLOATS (2048 + 128 + 128*132)
#define SCORE_SMEM_BYTES  (SCORE_SMEM_FLOATS * 4)

__device__ float g_qp[QSPLIT * QP_STRIDE];
__device__ float g_kp[KSPLIT * KP_STRIDE];
__device__ float g_q[kB * kDEC * kU];
__device__ float g_k[kB * kENC * kU];
__device__ float g_cp[kB * CSPLIT * CP_STRIDE];
__device__ float g_sc[kB * kDEC * kENC];   // raw masked scores

__device__ __forceinline__ float tanh_approx(float x) {
    float y;
    asm("tanh.approx.f32 %0, %1;" : "=f"(y) : "f"(x));
    return y;
}
__device__ __forceinline__ unsigned long long pack2(float x, float y) {
    unsigned long long r;
    asm("mov.b64 %0, {%1, %2};" : "=l"(r) : "f"(x), "f"(y));
    return r;
}
__device__ __forceinline__ float2 unpack2(unsigned long long v) {
    float2 f;
    asm("mov.b64 {%0, %1}, %2;" : "=f"(f.x), "=f"(f.y) : "l"(v));
    return f;
}
__device__ __forceinline__ void fma2(unsigned long long& d,
                                     unsigned long long a, unsigned long long b) {
    asm("fma.rn.f32x2 %0, %1, %2, %0;" : "+l"(d) : "l"(a), "l"(b));
}

// ---------------------------------------------------------------------------
// Conflict-free f32x2 GEMM core. 128x128 tile, 256 threads.
// Thread (tx,ty) owns rows {ty*4+i, 64+ty*4+i} x cols {tx*4.., 64+tx*4..}.
// ---------------------------------------------------------------------------
#define GEMM_CORE(Aptr, Bptr, Cb, Kstride, Nval, Klocal, m0, n0)               \
{                                                                              \
    const int tid = threadIdx.x;                                               \
    const int tx = tid & 15, ty = tid >> 4;                                    \
    const int am = tid >> 1,  ak = (tid & 1) * 8;                              \
    const int bk = tid >> 4,  bn = (tid & 15) * 8;                             \
    const float* Ap = (Aptr) + (long)(m0 + am) * (Kstride) + ak;               \
    const float* Bp = (Bptr) + (long)bk * (Nval) + n0 + bn;                    \
    unsigned long long acc[8][4];                                              \
    _Pragma("unroll")                                                          \
    for (int i = 0; i < 8; i++) { acc[i][0]=0; acc[i][1]=0; acc[i][2]=0; acc[i][3]=0; } \
    float4 a0 = *(const float4*)(Ap);                                          \
    float4 a1 = *(const float4*)(Ap + 4);                                      \
    float4 b0 = *(const float4*)(Bp);                                          \
    float4 b1 = *(const float4*)(Bp + 4);                                      \
    for (int kt = 0; kt < (Klocal); kt += 16) {                                \
        As[ak + 0][am] = a0.x; As[ak + 1][am] = a0.y;                          \
        As[ak + 2][am] = a0.z; As[ak + 3][am] = a0.w;                          \
        As[ak + 4][am] = a1.x; As[ak + 5][am] = a1.y;                          \
        As[ak + 6][am] = a1.z; As[ak + 7][am] = a1.w;                          \
        *(float4*)&Bs[bk][bn]     = b0;                                        \
        *(float4*)&Bs[bk][bn + 4] = b1;                                        \
        __syncthreads();                                                       \
        int kn = (kt + 16 < (Klocal)) ? kt + 16 : 0;                           \
        a0 = *(const float4*)(Ap + kn);                                        \
        a1 = *(const float4*)(Ap + kn + 4);                                    \
        b0 = *(const float4*)(Bp + (long)kn * (Nval));                         \
        b1 = *(const float4*)(Bp + (long)kn * (Nval) + 4);                     \
        _Pragma("unroll")                                                      \
        for (int kk = 0; kk < 16; kk++) {                                      \
            float4 av0 = *(const float4*)&As[kk][ty * 4];                      \
            float4 av1 = *(const float4*)&As[kk][64 + ty * 4];                 \
            float4 bv0 = *(const float4*)&Bs[kk][tx * 4];                      \
            float4 bv1 = *(const float4*)&Bs[kk][64 + tx * 4];                 \
            unsigned long long bp0 = pack2(bv0.x, bv0.y);                      \
            unsigned long long bp1 = pack2(bv0.z, bv0.w);                      \
            unsigned long long bp2 = pack2(bv1.x, bv1.y);                      \
            unsigned long long bp3 = pack2(bv1.z, bv1.w);                      \
            float av[8] = {av0.x, av0.y, av0.z, av0.w, av1.x, av1.y, av1.z, av1.w}; \
            _Pragma("unroll")                                                  \
            for (int i = 0; i < 8; i++) {                                      \
                unsigned long long ap = pack2(av[i], av[i]);                   \
                fma2(acc[i][0], ap, bp0);                                      \
                fma2(acc[i][1], ap, bp1);                                      \
                fma2(acc[i][2], ap, bp2);                                      \
                fma2(acc[i][3], ap, bp3);                                      \
            }                                                                  \
        }                                                                      \
        __syncthreads();                                                       \
    }                                                                          \
    _Pragma("unroll")                                                          \
    for (int i = 0; i < 8; i++) {                                              \
        int row = (i < 4) ? (m0 + ty * 4 + i) : (m0 + 64 + ty * 4 + i - 4);    \
        float2 c0 = unpack2(acc[i][0]), c1 = unpack2(acc[i][1]);               \
        float2 c2 = unpack2(acc[i][2]), c3 = unpack2(acc[i][3]);               \
        float* crow = (Cb) + (long)row * (Nval) + n0;                          \
        *(float4*)(crow + tx * 4)      = make_float4(c0.x, c0.y, c1.x, c1.y);  \
        *(float4*)(crow + 64 + tx * 4) = make_float4(c2.x, c2.y, c3.x, c3.y);  \
    }                                                                          \
}

// ---------------------------------------------------------------------------
// Combined q/k projection, balanced K-split (all blocks: 128x128x64).
// ---------------------------------------------------------------------------
__global__ __launch_bounds__(256, 2) void proj_kernel(
    const float* __restrict__ query, const float* __restrict__ W1,
    const float* __restrict__ value, const float* __restrict__ W2)
{
    __shared__ float As[16][132];
    __shared__ float Bs[16][128];

    const int z = blockIdx.x;
    const float *Ab, *Bb;
    float* Cb;
    int kbeg, m0;
    if (z < 64) {
        int part = z >> 3, mt = z & 7;
        Ab = query; Bb = W1; Cb = g_qp + (long)part * QP_STRIDE;
        kbeg = part * 64; m0 = mt * 128;
    } else {
        int t = z - 64;
        int part = t >> 5, mt = t & 31;
        Ab = value; Bb = W2; Cb = g_kp + (long)part * KP_STRIDE;
        kbeg = part * 64; m0 = mt * 128;
    }
    const float* Abk = Ab + kbeg;
    const float* Bbk = Bb + (long)kbeg * 128;
    GEMM_CORE(Abk, Bbk, Cb, 512, 128, 64, m0, 0)
}

// ---------------------------------------------------------------------------
// ctx partial GEMM: per (batch, split) of (256,1024)@(1024,512).
// ---------------------------------------------------------------------------
__global__ __launch_bounds__(256, 2) void gemm128(
    const float* __restrict__ A, const float* __restrict__ Bm, float* __restrict__ C,
    int M, int N, int K, int nsplit, long sA, long sB)
{
    __shared__ float As[16][132];
    __shared__ float Bs[16][128];

    const int z = blockIdx.z;
    const int b = z / nsplit;
    const int s = z - b * nsplit;
    const int Klocal = K / nsplit;
    const int kbeg = s * Klocal;

    const float* Ab = A + (long)b * sA + kbeg;
    const float* Bb = Bm + (long)b * sB + (long)kbeg * N;
    float*       Cb = C + (long)z * M * N;

    const int m0 = blockIdx.y * 128;
    const int n0 = blockIdx.x * 128;
    GEMM_CORE(Ab, Bb, Cb, K, N, Klocal, m0, n0)
}

// ---------------------------------------------------------------------------
// Sum projection K-split parts: g_qp(8) -> g_q, g_kp(8) -> g_k.
// ---------------------------------------------------------------------------
#define QN (kB * kDEC * kU / 4)    // 32768 float4
#define KN (kB * kENC * kU / 4)    // 131072 float4
__global__ __launch_bounds__(256) void reduce_qk_kernel()
{
    int idx = blockIdx.x * 256 + threadIdx.x;
    if (idx < QN) {
        const float4* p = (const float4*)g_qp;
        float4 s = make_float4(0.f, 0.f, 0.f, 0.f);
#pragma unroll
        for (int j = 0; j < QSPLIT; j++) {
            float4 v = p[idx + j * (QP_STRIDE / 4)];
            s.x += v.x; s.y += v.y; s.z += v.z; s.w += v.w;
        }
        ((float4*)g_q)[idx] = s;
    } else {
        int i = idx - QN;
        const float4* p = (const float4*)g_kp;
        float4 s = make_float4(0.f, 0.f, 0.f, 0.f);
#pragma unroll
        for (int j = 0; j < KSPLIT; j++) {
            float4 v = p[i + j * (KP_STRIDE / 4)];
            s.x += v.x; s.y += v.y; s.z += v.z; s.w += v.w;
        }
        ((float4*)g_k)[i] = s;
    }
}

// ---------------------------------------------------------------------------
// ctx = sum of CSPLIT K-split parts per batch.
// ---------------------------------------------------------------------------
__global__ __launch_bounds__(256) void reduce_ctx_kernel(float4* __restrict__ out)
{
    const float4* p = (const float4*)g_cp;
    const int idx = blockIdx.x * 256 + threadIdx.x;
    const int slice = CP_STRIDE / 4;
    const int b = idx / slice;
    const int i = idx - b * slice;
    const float4* base = p + (long)(b * CSPLIT) * slice + i;
    float4 s = make_float4(0.f, 0.f, 0.f, 0.f);
#pragma unroll
    for (int j = 0; j < CSPLIT; j++) {
        float4 v = base[(long)j * slice];
        s.x += v.x; s.y += v.y; s.z += v.z; s.w += v.w;
    }
    out[idx] = s;
}

// ---------------------------------------------------------------------------
// Additive scores (masked) -> g_sc. One block = (b, 16 queries, 128 enc rows).
// grid (8, 16, 4), 512 threads. Single k tile per block: stage once, one
// barrier, compute. Warp w = query q0+w; lane handles 4 e-rows.
// ---------------------------------------------------------------------------
__global__ __launch_bounds__(512) void score_kernel(
    const float* __restrict__ scale, const int* __restrict__ mask)
{
    extern __shared__ float sm[];
    float* qs  = sm;                  // 16 * 128
    float* scl = qs + 16 * kU;        // 128
    float* ks  = scl + kU;            // 128 * 132

    const int b   = blockIdx.z;
    const int q0  = blockIdx.y * 16;
    const int et  = blockIdx.x * 128;
    const int tid = threadIdx.x;

    // stage 16 query rows (512 float4s, one per thread)
    ((float4*)qs)[tid] = ((const float4*)(g_q + (long)(b * kDEC + q0) * kU))[tid];
    if (tid < kU) scl[tid] = scale[tid];

    // stage 128-row k tile (4096 float4s / 512 threads = 8 each)
    const float* kbase = g_k + (long)b * kENC * kU;
#pragma unroll
    for (int i = 0; i < 8; i++) {
        int f4  = tid + i * 512;
        int row = f4 >> 5;
        int col = (f4 & 31) * 4;
        *(float4*)(ks + row * 132 + col) =
            *(const float4*)(kbase + (long)(et + row) * kU + col);
    }
    __syncthreads();

    const int q    = tid >> 5;
    const int lane = tid & 31;
    const int* mrow = mask + b * kENC;
    const float* qr = qs + q * kU;
    float* srow = g_sc + (long)(b * kDEC + q0 + q) * kENC;

    const float* k0 = ks + (lane +  0) * 132;
    const float* k1 = ks + (lane + 32) * 132;
    const float* k2 = ks + (lane + 64) * 132;
    const float* k3 = ks + (lane + 96) * 132;
    float s0 = 0.f, s1 = 0.f, s2 = 0.f, s3 = 0.f;
#pragma unroll
    for (int u = 0; u < kU; u += 4) {
        float4 qv = *(const float4*)(qr + u);
        float4 sv = *(const float4*)(scl + u);
        float4 a = *(const float4*)(k0 + u);
        float4 c = *(const float4*)(k1 + u);
        float4 d = *(const float4*)(k2 + u);
        float4 e = *(const float4*)(k3 + u);
        s0 = fmaf(sv.x, tanh_approx(qv.x + a.x), s0);
        s0 = fmaf(sv.y, tanh_approx(qv.y + a.y), s0);
        s0 = fmaf(sv.z, tanh_approx(qv.z + a.z), s0);
        s0 = fmaf(sv.w, tanh_approx(qv.w + a.w), s0);
        s1 = fmaf(sv.x, tanh_approx(qv.x + c.x), s1);
        s1 = fmaf(sv.y, tanh_approx(qv.y + c.y), s1);
        s1 = fmaf(sv.z, tanh_approx(qv.z + c.z), s1);
        s1 = fmaf(sv.w, tanh_approx(qv.w + c.w), s1);
        s2 = fmaf(sv.x, tanh_approx(qv.x + d.x), s2);
        s2 = fmaf(sv.y, tanh_approx(qv.y + d.y), s2);
        s2 = fmaf(sv.z, tanh_approx(qv.z + d.z), s2);
        s2 = fmaf(sv.w, tanh_approx(qv.w + d.w), s2);
        s3 = fmaf(sv.x, tanh_approx(qv.x + e.x), s3);
        s3 = fmaf(sv.y, tanh_approx(qv.y + e.y), s3);
        s3 = fmaf(sv.z, tanh_approx(qv.z + e.z), s3);
        s3 = fmaf(sv.w, tanh_approx(qv.w + e.w), s3);
    }
    int e0 = et + lane, e1 = e0 + 32, e2 = e0 + 64, e3 = e0 + 96;
    srow[e0] = (mrow[e0] == 0) ? -1e9f : s0;
    srow[e1] = (mrow[e1] == 0) ? -1e9f : s1;
    srow[e2] = (mrow[e2] == 0) ? -1e9f : s2;
    srow[e3] = (mrow[e3] == 0) ? -1e9f : s3;
}

// ---------------------------------------------------------------------------
// Softmax over g_sc rows -> wts. FOUR warps per row, one row per 128-thread
// block, grid 1024. Two smem combines; lane holds 8 floats.
// ---------------------------------------------------------------------------
__global__ __launch_bounds__(128) void softmax_kernel(float* __restrict__ wts)
{
    __shared__ float red[8];
    const int r    = blockIdx.x;
    const int w    = threadIdx.x >> 5;
    const int lane = threadIdx.x & 31;

    const float4* row4 = (const float4*)(g_sc + (long)r * kENC) + w * 64;

    float4 v0 = row4[lane];
    float4 v1 = row4[lane + 32];
    float mx = fmaxf(fmaxf(fmaxf(v0.x, v0.y), fmaxf(v0.z, v0.w)),
                     fmaxf(fmaxf(v1.x, v1.y), fmaxf(v1.z, v1.w)));
#pragma unroll
    for (int off = 16; off > 0; off >>= 1)
        mx = fmaxf(mx, __shfl_xor_sync(0xffffffffu, mx, off));
    if (lane == 0) red[w] = mx;
    __syncthreads();
    mx = fmaxf(fmaxf(red[0], red[1]), fmaxf(red[2], red[3]));

    v0.x = __expf(v0.x - mx); v0.y = __expf(v0.y - mx);
    v0.z = __expf(v0.z - mx); v0.w = __expf(v0.w - mx);
    v1.x = __expf(v1.x - mx); v1.y = __expf(v1.y - mx);
    v1.z = __expf(v1.z - mx); v1.w = __expf(v1.w - mx);
    float ssum = v0.x + v0.y + v0.z + v0.w + v1.x + v1.y + v1.z + v1.w;
#pragma unroll
    for (int off = 16; off > 0; off >>= 1)
        ssum += __shfl_xor_sync(0xffffffffu, ssum, off);
    if (lane == 0) red[4 + w] = ssum;
    __syncthreads();
    ssum = (red[4] + red[5]) + (red[6] + red[7]);
    const float inv = 1.0f / ssum;

    float4* w4 = (float4*)(wts + (long)r * kENC) + w * 64;
    w4[lane]      = make_float4(v0.x * inv, v0.y * inv, v0.z * inv, v0.w * inv);
    w4[lane + 32] = make_float4(v1.x * inv, v1.y * inv, v1.z * inv, v1.w * inv);
}

// ---------------------------------------------------------------------------
extern "C" void kernel_launch(void* const* d_in, const int* in_sizes, int n_in,
                              void* d_out, int out_size)
{
    const float* query = (const float*)d_in[0];
    const float* value = (const float*)d_in[1];
    const int*   mask  = (const int*)d_in[2];
    const float* W1    = (const float*)d_in[3];
    const float* W2    = (const float*)d_in[4];
    const float* scale = (const float*)d_in[5];

    float* ctx = (float*)d_out;                          // (B, DEC, HID)
    float* wts = ctx + (size_t)kB * kDEC * kHID;         // (B, DEC, ENC)

    float* cp;
    cudaGetSymbolAddress((void**)&cp, g_cp);

    cudaFuncSetAttribute(score_kernel,
        cudaFuncAttributeMaxDynamicSharedMemorySize, SCORE_SMEM_BYTES);

    // combined q+k projections, balanced split (320 blocks)
    proj_kernel<<<320, 256>>>(query, W1, value, W2);

    // sum projection parts
    reduce_qk_kernel<<<(QN + KN) / 256, 256>>>();

    // masked scores (grid 512, 512 threads, 2 CTAs/SM, single tile/block)
    score_kernel<<<dim3(8, 16, kB), 512, SCORE_SMEM_BYTES>>>(scale, mask);

    // softmax -> weights (4 warps per row, grid 1024)
    softmax_kernel<<<kB * kDEC, 128>>>(wts);

    // context: per-batch (256,1024)@(1024,512), split 8 -> 256 blocks
    gemm128<<<dim3(4, 2, kB * CSPLIT), 256>>>(wts, value, cp, 256, 512, 1024, CSPLIT,
                                              (long)kDEC * kENC, (long)kENC * kHID);

    // sum ctx parts -> d_out
    reduce_ctx_kernel<<<(kB * CP_STRIDE / 4) / 256, 256>>>((float4*)ctx);
}

// round 14
// speedup vs baseline: 1.0663x; 1.0663x over previous
#include <cuda_runtime.h>
#include <cstdint>

#define kB   4
#define kDEC 256
#define kENC 1024
#define kHID 512
#define kU   128

#define QSPLIT 8
#define KSPLIT 8
#define CSPLIT 8

#define QP_STRIDE (1024 * 128)   // one qproj part
#define KP_STRIDE (4096 * 128)   // one kproj part
#define CP_STRIDE (256 * 512)    // one ctx part

// score smem: 2048(qs) + 128(scl) + 128*132(ks) floats = 76,288 B -> 2 CTAs/SM
#define SCORE_SMEM_FLOATS (2048 + 128 + 128*132)
#define SCORE_SMEM_BYTES  (SCORE_SMEM_FLOATS * 4)

__device__ float g_qp[QSPLIT * QP_STRIDE];
__device__ float g_kp[KSPLIT * KP_STRIDE];
__device__ float g_q[kB * kDEC * kU];
__device__ float g_k[kB * kENC * kU];
__device__ float g_cp[kB * CSPLIT * CP_STRIDE];
__device__ float g_sc[kB * kDEC * kENC];   // raw masked scores

__device__ __forceinline__ float tanh_approx(float x) {
    float y;
    asm("tanh.approx.f32 %0, %1;" : "=f"(y) : "f"(x));
    return y;
}
__device__ __forceinline__ unsigned long long pack2(float x, float y) {
    unsigned long long r;
    asm("mov.b64 %0, {%1, %2};" : "=l"(r) : "f"(x), "f"(y));
    return r;
}
__device__ __forceinline__ float2 unpack2(unsigned long long v) {
    float2 f;
    asm("mov.b64 {%0, %1}, %2;" : "=f"(f.x), "=f"(f.y) : "l"(v));
    return f;
}
__device__ __forceinline__ void fma2(unsigned long long& d,
                                     unsigned long long a, unsigned long long b) {
    asm("fma.rn.f32x2 %0, %1, %2, %0;" : "+l"(d) : "l"(a), "l"(b));
}

// ---------------------------------------------------------------------------
// Conflict-free f32x2 GEMM core, DOUBLE-BUFFERED smem, 128x128 tile, 256 thr.
// Per 16-K chunk: issue next LDGs -> compute cur buffer -> store next buffer
// -> one barrier. Thread (tx,ty) owns rows {ty*4+i, 64+ty*4+i} x cols
// {tx*4.., 64+tx*4..} (B LDS.128 phases 128B-contiguous -> conflict-free).
// Requires: __shared__ float As[2][16][132]; __shared__ float Bs[2][16][128];
// ---------------------------------------------------------------------------
#define GEMM_CORE(Aptr, Bptr, Cb, Kstride, Nval, Klocal, m0, n0)               \
{                                                                              \
    const int tid = threadIdx.x;                                               \
    const int tx = tid & 15, ty = tid >> 4;                                    \
    const int am = tid >> 1,  ak = (tid & 1) * 8;                              \
    const int bk = tid >> 4,  bn = (tid & 15) * 8;                             \
    const float* Ap = (Aptr) + (long)(m0 + am) * (Kstride) + ak;               \
    const float* Bp = (Bptr) + (long)bk * (Nval) + n0 + bn;                    \
    unsigned long long acc[8][4];                                              \
    _Pragma("unroll")                                                          \
    for (int i = 0; i < 8; i++) { acc[i][0]=0; acc[i][1]=0; acc[i][2]=0; acc[i][3]=0; } \
    float4 a0 = *(const float4*)(Ap);                                          \
    float4 a1 = *(const float4*)(Ap + 4);                                      \
    float4 b0 = *(const float4*)(Bp);                                          \
    float4 b1 = *(const float4*)(Bp + 4);                                      \
    As[0][ak + 0][am] = a0.x; As[0][ak + 1][am] = a0.y;                        \
    As[0][ak + 2][am] = a0.z; As[0][ak + 3][am] = a0.w;                        \
    As[0][ak + 4][am] = a1.x; As[0][ak + 5][am] = a1.y;                        \
    As[0][ak + 6][am] = a1.z; As[0][ak + 7][am] = a1.w;                        \
    *(float4*)&Bs[0][bk][bn]     = b0;                                         \
    *(float4*)&Bs[0][bk][bn + 4] = b1;                                         \
    __syncthreads();                                                           \
    int buf = 0;                                                               \
    for (int kt = 0; kt < (Klocal); kt += 16) {                                \
        const int kn = kt + 16;                                                \
        const bool more = (kn < (Klocal));                                     \
        if (more) {                                                            \
            a0 = *(const float4*)(Ap + kn);                                    \
            a1 = *(const float4*)(Ap + kn + 4);                                \
            b0 = *(const float4*)(Bp + (long)kn * (Nval));                     \
            b1 = *(const float4*)(Bp + (long)kn * (Nval) + 4);                 \
        }                                                                      \
        _Pragma("unroll")                                                      \
        for (int kk = 0; kk < 16; kk++) {                                      \
            float4 av0 = *(const float4*)&As[buf][kk][ty * 4];                 \
            float4 av1 = *(const float4*)&As[buf][kk][64 + ty * 4];            \
            float4 bv0 = *(const float4*)&Bs[buf][kk][tx * 4];                 \
            float4 bv1 = *(const float4*)&Bs[buf][kk][64 + tx * 4];            \
            unsigned long long bp0 = pack2(bv0.x, bv0.y);                      \
            unsigned long long bp1 = pack2(bv0.z, bv0.w);                      \
            unsigned long long bp2 = pack2(bv1.x, bv1.y);                      \
            unsigned long long bp3 = pack2(bv1.z, bv1.w);                      \
            float av[8] = {av0.x, av0.y, av0.z, av0.w, av1.x, av1.y, av1.z, av1.w}; \
            _Pragma("unroll")                                                  \
            for (int i = 0; i < 8; i++) {                                      \
                unsigned long long ap = pack2(av[i], av[i]);                   \
                fma2(acc[i][0], ap, bp0);                                      \
                fma2(acc[i][1], ap, bp1);                                      \
                fma2(acc[i][2], ap, bp2);                                      \
                fma2(acc[i][3], ap, bp3);                                      \
            }                                                                  \
        }                                                                      \
        if (more) {                                                            \
            const int nb = buf ^ 1;                                            \
            As[nb][ak + 0][am] = a0.x; As[nb][ak + 1][am] = a0.y;              \
            As[nb][ak + 2][am] = a0.z; As[nb][ak + 3][am] = a0.w;              \
            As[nb][ak + 4][am] = a1.x; As[nb][ak + 5][am] = a1.y;              \
            As[nb][ak + 6][am] = a1.z; As[nb][ak + 7][am] = a1.w;              \
            *(float4*)&Bs[nb][bk][bn]     = b0;                                \
            *(float4*)&Bs[nb][bk][bn + 4] = b1;                                \
            __syncthreads();                                                   \
            buf = nb;                                                          \
        }                                                                      \
    }                                                                          \
    _Pragma("unroll")                                                          \
    for (int i = 0; i < 8; i++) {                                              \
        int row = (i < 4) ? (m0 + ty * 4 + i) : (m0 + 64 + ty * 4 + i - 4);    \
        float2 c0 = unpack2(acc[i][0]), c1 = unpack2(acc[i][1]);               \
        float2 c2 = unpack2(acc[i][2]), c3 = unpack2(acc[i][3]);               \
        float* crow = (Cb) + (long)row * (Nval) + n0;                          \
        *(float4*)(crow + tx * 4)      = make_float4(c0.x, c0.y, c1.x, c1.y);  \
        *(float4*)(crow + 64 + tx * 4) = make_float4(c2.x, c2.y, c3.x, c3.y);  \
    }                                                                          \
}

// ---------------------------------------------------------------------------
// Combined q/k projection, balanced K-split (all blocks: 128x128x64).
// ---------------------------------------------------------------------------
__global__ __launch_bounds__(256, 2) void proj_kernel(
    const float* __restrict__ query, const float* __restrict__ W1,
    const float* __restrict__ value, const float* __restrict__ W2)
{
    __shared__ float As[2][16][132];
    __shared__ float Bs[2][16][128];

    const int z = blockIdx.x;
    const float *Ab, *Bb;
    float* Cb;
    int kbeg, m0;
    if (z < 64) {
        int part = z >> 3, mt = z & 7;
        Ab = query; Bb = W1; Cb = g_qp + (long)part * QP_STRIDE;
        kbeg = part * 64; m0 = mt * 128;
    } else {
        int t = z - 64;
        int part = t >> 5, mt = t & 31;
        Ab = value; Bb = W2; Cb = g_kp + (long)part * KP_STRIDE;
        kbeg = part * 64; m0 = mt * 128;
    }
    const float* Abk = Ab + kbeg;
    const float* Bbk = Bb + (long)kbeg * 128;
    GEMM_CORE(Abk, Bbk, Cb, 512, 128, 64, m0, 0)
}

// ---------------------------------------------------------------------------
// ctx partial GEMM: per (batch, split) of (256,1024)@(1024,512).
// ---------------------------------------------------------------------------
__global__ __launch_bounds__(256, 2) void gemm128(
    const float* __restrict__ A, const float* __restrict__ Bm, float* __restrict__ C,
    int M, int N, int K, int nsplit, long sA, long sB)
{
    __shared__ float As[2][16][132];
    __shared__ float Bs[2][16][128];

    const int z = blockIdx.z;
    const int b = z / nsplit;
    const int s = z - b * nsplit;
    const int Klocal = K / nsplit;
    const int kbeg = s * Klocal;

    const float* Ab = A + (long)b * sA + kbeg;
    const float* Bb = Bm + (long)b * sB + (long)kbeg * N;
    float*       Cb = C + (long)z * M * N;

    const int m0 = blockIdx.y * 128;
    const int n0 = blockIdx.x * 128;
    GEMM_CORE(Ab, Bb, Cb, K, N, Klocal, m0, n0)
}

// ---------------------------------------------------------------------------
// Sum projection K-split parts: g_qp(8) -> g_q, g_kp(8) -> g_k.
// ---------------------------------------------------------------------------
#define QN (kB * kDEC * kU / 4)    // 32768 float4
#define KN (kB * kENC * kU / 4)    // 131072 float4
__global__ __launch_bounds__(256) void reduce_qk_kernel()
{
    int idx = blockIdx.x * 256 + threadIdx.x;
    if (idx < QN) {
        const float4* p = (const float4*)g_qp;
        float4 s = make_float4(0.f, 0.f, 0.f, 0.f);
#pragma unroll
        for (int j = 0; j < QSPLIT; j++) {
            float4 v = p[idx + j * (QP_STRIDE / 4)];
            s.x += v.x; s.y += v.y; s.z += v.z; s.w += v.w;
        }
        ((float4*)g_q)[idx] = s;
    } else {
        int i = idx - QN;
        const float4* p = (const float4*)g_kp;
        float4 s = make_float4(0.f, 0.f, 0.f, 0.f);
#pragma unroll
        for (int j = 0; j < KSPLIT; j++) {
            float4 v = p[i + j * (KP_STRIDE / 4)];
            s.x += v.x; s.y += v.y; s.z += v.z; s.w += v.w;
        }
        ((float4*)g_k)[i] = s;
    }
}

// ---------------------------------------------------------------------------
// ctx = sum of CSPLIT K-split parts per batch.
// ---------------------------------------------------------------------------
__global__ __launch_bounds__(256) void reduce_ctx_kernel(float4* __restrict__ out)
{
    const float4* p = (const float4*)g_cp;
    const int idx = blockIdx.x * 256 + threadIdx.x;
    const int slice = CP_STRIDE / 4;
    const int b = idx / slice;
    const int i = idx - b * slice;
    const float4* base = p + (long)(b * CSPLIT) * slice + i;
    float4 s = make_float4(0.f, 0.f, 0.f, 0.f);
#pragma unroll
    for (int j = 0; j < CSPLIT; j++) {
        float4 v = base[(long)j * slice];
        s.x += v.x; s.y += v.y; s.z += v.z; s.w += v.w;
    }
    out[idx] = s;
}

// ---------------------------------------------------------------------------
// Additive scores (masked) -> g_sc. One block = (b, 16 queries, 128 enc rows).
// grid (8, 16, 4), 512 threads. Single k tile per block.
// ---------------------------------------------------------------------------
__global__ __launch_bounds__(512) void score_kernel(
    const float* __restrict__ scale, const int* __restrict__ mask)
{
    extern __shared__ float sm[];
    float* qs  = sm;                  // 16 * 128
    float* scl = qs + 16 * kU;        // 128
    float* ks  = scl + kU;            // 128 * 132

    const int b   = blockIdx.z;
    const int q0  = blockIdx.y * 16;
    const int et  = blockIdx.x * 128;
    const int tid = threadIdx.x;

    ((float4*)qs)[tid] = ((const float4*)(g_q + (long)(b * kDEC + q0) * kU))[tid];
    if (tid < kU) scl[tid] = scale[tid];

    const float* kbase = g_k + (long)b * kENC * kU;
#pragma unroll
    for (int i = 0; i < 8; i++) {
        int f4  = tid + i * 512;
        int row = f4 >> 5;
        int col = (f4 & 31) * 4;
        *(float4*)(ks + row * 132 + col) =
            *(const float4*)(kbase + (long)(et + row) * kU + col);
    }
    __syncthreads();

    const int q    = tid >> 5;
    const int lane = tid & 31;
    const int* mrow = mask + b * kENC;
    const float* qr = qs + q * kU;
    float* srow = g_sc + (long)(b * kDEC + q0 + q) * kENC;

    const float* k0 = ks + (lane +  0) * 132;
    const float* k1 = ks + (lane + 32) * 132;
    const float* k2 = ks + (lane + 64) * 132;
    const float* k3 = ks + (lane + 96) * 132;
    float s0 = 0.f, s1 = 0.f, s2 = 0.f, s3 = 0.f;
#pragma unroll
    for (int u = 0; u < kU; u += 4) {
        float4 qv = *(const float4*)(qr + u);
        float4 sv = *(const float4*)(scl + u);
        float4 a = *(const float4*)(k0 + u);
        float4 c = *(const float4*)(k1 + u);
        float4 d = *(const float4*)(k2 + u);
        float4 e = *(const float4*)(k3 + u);
        s0 = fmaf(sv.x, tanh_approx(qv.x + a.x), s0);
        s0 = fmaf(sv.y, tanh_approx(qv.y + a.y), s0);
        s0 = fmaf(sv.z, tanh_approx(qv.z + a.z), s0);
        s0 = fmaf(sv.w, tanh_approx(qv.w + a.w), s0);
        s1 = fmaf(sv.x, tanh_approx(qv.x + c.x), s1);
        s1 = fmaf(sv.y, tanh_approx(qv.y + c.y), s1);
        s1 = fmaf(sv.z, tanh_approx(qv.z + c.z), s1);
        s1 = fmaf(sv.w, tanh_approx(qv.w + c.w), s1);
        s2 = fmaf(sv.x, tanh_approx(qv.x + d.x), s2);
        s2 = fmaf(sv.y, tanh_approx(qv.y + d.y), s2);
        s2 = fmaf(sv.z, tanh_approx(qv.z + d.z), s2);
        s2 = fmaf(sv.w, tanh_approx(qv.w + d.w), s2);
        s3 = fmaf(sv.x, tanh_approx(qv.x + e.x), s3);
        s3 = fmaf(sv.y, tanh_approx(qv.y + e.y), s3);
        s3 = fmaf(sv.z, tanh_approx(qv.z + e.z), s3);
        s3 = fmaf(sv.w, tanh_approx(qv.w + e.w), s3);
    }
    int e0 = et + lane, e1 = e0 + 32, e2 = e0 + 64, e3 = e0 + 96;
    srow[e0] = (mrow[e0] == 0) ? -1e9f : s0;
    srow[e1] = (mrow[e1] == 0) ? -1e9f : s1;
    srow[e2] = (mrow[e2] == 0) ? -1e9f : s2;
    srow[e3] = (mrow[e3] == 0) ? -1e9f : s3;
}

// ---------------------------------------------------------------------------
// Softmax over g_sc rows -> wts. 4 warps/row, 128-thread blocks, grid 1024.
// ---------------------------------------------------------------------------
__global__ __launch_bounds__(128) void softmax_kernel(float* __restrict__ wts)
{
    __shared__ float red[8];
    const int r    = blockIdx.x;
    const int w    = threadIdx.x >> 5;
    const int lane = threadIdx.x & 31;

    const float4* row4 = (const float4*)(g_sc + (long)r * kENC) + w * 64;

    float4 v0 = row4[lane];
    float4 v1 = row4[lane + 32];
    float mx = fmaxf(fmaxf(fmaxf(v0.x, v0.y), fmaxf(v0.z, v0.w)),
                     fmaxf(fmaxf(v1.x, v1.y), fmaxf(v1.z, v1.w)));
#pragma unroll
    for (int off = 16; off > 0; off >>= 1)
        mx = fmaxf(mx, __shfl_xor_sync(0xffffffffu, mx, off));
    if (lane == 0) red[w] = mx;
    __syncthreads();
    mx = fmaxf(fmaxf(red[0], red[1]), fmaxf(red[2], red[3]));

    v0.x = __expf(v0.x - mx); v0.y = __expf(v0.y - mx);
    v0.z = __expf(v0.z - mx); v0.w = __expf(v0.w - mx);
    v1.x = __expf(v1.x - mx); v1.y = __expf(v1.y - mx);
    v1.z = __expf(v1.z - mx); v1.w = __expf(v1.w - mx);
    float ssum = v0.x + v0.y + v0.z + v0.w + v1.x + v1.y + v1.z + v1.w;
#pragma unroll
    for (int off = 16; off > 0; off >>= 1)
        ssum += __shfl_xor_sync(0xffffffffu, ssum, off);
    if (lane == 0) red[4 + w] = ssum;
    __syncthreads();
    ssum = (red[4] + red[5]) + (red[6] + red[7]);
    const float inv = 1.0f / ssum;

    float4* w4 = (float4*)(wts + (long)r * kENC) + w * 64;
    w4[lane]      = make_float4(v0.x * inv, v0.y * inv, v0.z * inv, v0.w * inv);
    w4[lane + 32] = make_float4(v1.x * inv, v1.y * inv, v1.z * inv, v1.w * inv);
}

// ---------------------------------------------------------------------------
extern "C" void kernel_launch(void* const* d_in, const int* in_sizes, int n_in,
                              void* d_out, int out_size)
{
    const float* query = (const float*)d_in[0];
    const float* value = (const float*)d_in[1];
    const int*   mask  = (const int*)d_in[2];
    const float* W1    = (const float*)d_in[3];
    const float* W2    = (const float*)d_in[4];
    const float* scale = (const float*)d_in[5];

    float* ctx = (float*)d_out;                          // (B, DEC, HID)
    float* wts = ctx + (size_t)kB * kDEC * kHID;         // (B, DEC, ENC)

    float* cp;
    cudaGetSymbolAddress((void**)&cp, g_cp);

    cudaFuncSetAttribute(score_kernel,
        cudaFuncAttributeMaxDynamicSharedMemorySize, SCORE_SMEM_BYTES);

    // combined q+k projections, balanced split (320 blocks)
    proj_kernel<<<320, 256>>>(query, W1, value, W2);

    // sum projection parts
    reduce_qk_kernel<<<(QN + KN) / 256, 256>>>();

    // masked scores (grid 512, 512 threads, 2 CTAs/SM, single tile/block)
    score_kernel<<<dim3(8, 16, kB), 512, SCORE_SMEM_BYTES>>>(scale, mask);

    // softmax -> weights (4 warps per row, grid 1024)
    softmax_kernel<<<kB * kDEC, 128>>>(wts);

    // context: per-batch (256,1024)@(1024,512), split 8 -> 256 blocks
    gemm128<<<dim3(4, 2, kB * CSPLIT), 256>>>(wts, value, cp, 256, 512, 1024, CSPLIT,
                                              (long)kDEC * kENC, (long)kENC * kHID);

    // sum ctx parts -> d_out
    reduce_ctx_kernel<<<(kB * CP_STRIDE / 4) / 256, 256>>>((float4*)ctx);
}